// round 13
// baseline (speedup 1.0000x reference)
#include <cuda_runtime.h>
#include <cstdint>

// Problem shape (fixed for this dataset entry)
#define B_    2
#define N_    50000
#define C_    64
#define M_    50000
#define K_    16
#define H_    8
#define CMID_ 16

// Runtime-detected index width flag (int64 vs int32), set by detect kernel.
__device__ int g_idx_is64;

__global__ void detect_idx_kernel(const unsigned int* __restrict__ w) {
    if (threadIdx.x == 0 && blockIdx.x == 0) {
        int is64 = 1;
        #pragma unroll 1
        for (int i = 0; i < 256; i++) {
            if (w[2 * i + 1] != 0u) { is64 = 0; break; }
        }
        g_idx_is64 = is64;
    }
}

// One WARP per point; 4 points per 128-thread CTA.
// Tile (from R6, the lowest-L1 compute loop measured): cq = lane&15 owns 4
// contiguous channels [4cq,4cq+4) (exactly one guidance head, hd=cq>>1);
// wh = lane>>4 owns w half [8wh,8wh+8).
// Inner loop = FOUR memory instructions per k (vs 6 in the 131us R12):
//   1 gather LDG.128 (16 lanes cover the 256B feature row; 2-dup, 2 lines)
//   1 scalar guid LDS (broadcast) + 2 LDS.128 W (2 distinct addrs/warp)
// Accumulators pack along channels: acc[j]={out[4cq][w_j],out[4cq+1][w_j]},
// acc[8+j]={out[4cq+2][w_j],out[4cq+3][w_j]}, w_j = 8wh+j. The multiplier
// channel-pairs come packed straight from the gather load (2 mul.rn.f32x2).
// Epilogue = R12's proven swizzled smem bounce -> fully-coalesced STG.128.
__global__ void __launch_bounds__(128)
pcf_kernel(const float* __restrict__ feat,
           const void*  __restrict__ inds_raw,
           const float* __restrict__ guid,
           const float* __restrict__ wn,
           float* __restrict__ out)
{
    __shared__ __align__(16) float swn[4][K_ * CMID_];  // 4 x 1KB  weightnet
    __shared__ __align__(16) float sgd[4][K_ * H_];     // 4 x 512B guidance
    __shared__ __align__(16) float sout[4][1024];       // 4 x 4KB  output bounce
    __shared__ int sidx[4][K_];

    const int wid  = threadIdx.x >> 5;
    const int lane = threadIdx.x & 31;
    const int p    = blockIdx.x * 4 + wid;      // point id in [0, B*M)
    const int b    = (p >= M_) ? 1 : 0;
    const int cq   = lane & 15;                 // channel quad [4cq, 4cq+4)
    const int wh   = lane >> 4;                 // w half [8wh, 8wh+8)
    const int hd   = cq >> 1;                   // guidance head of those 4 ch

    // ---- per-warp staging: weightnet (1KB), guidance (512B), indices ----
    {
        const float4* wsrc = (const float4*)(wn + (size_t)p * (K_ * CMID_));
        float4* wdst = (float4*)(swn[wid]);
        wdst[lane]      = wsrc[lane];
        wdst[lane + 32] = wsrc[lane + 32];
        ((float4*)(sgd[wid]))[lane] = ((const float4*)(guid + (size_t)p * (K_ * H_)))[lane];
        if (lane < K_) {
            long long idx;
            if (g_idx_is64) idx = ((const long long*)inds_raw)[(size_t)p * K_ + lane];
            else            idx = (long long)((const int*)inds_raw)[(size_t)p * K_ + lane];
            sidx[wid][lane] = (int)idx;
        }
    }
    __syncwarp();

    // lane-fixed channel base: this lane's 4 channels start at 4*cq
    const float* fb = feat + (size_t)b * ((size_t)N_ * C_) + 4 * cq;

    unsigned long long acc[16];
    #pragma unroll
    for (int i = 0; i < 16; i++) acc[i] = 0ull;

    // depth-1 double buffer on the gather (one LDG.128 in flight)
    ulonglong2 A = *(const ulonglong2*)(fb + (size_t)sidx[wid][0] * C_);

    #pragma unroll 4
    for (int k = 0; k < K_; k++) {
        const ulonglong2 cur = A;
        if (k + 1 < K_)
            A = *(const ulonglong2*)(fb + (size_t)sidx[wid][k + 1] * C_);

        const float g = sgd[wid][k * H_ + hd];   // scalar broadcast LDS
        unsigned long long gg, s0, s1;
        asm("mov.b64 %0, {%1, %1};" : "=l"(gg) : "f"(g));
        asm("mul.rn.f32x2 %0, %1, %2;" : "=l"(s0) : "l"(cur.x), "l"(gg)); // ch {4cq,4cq+1}
        asm("mul.rn.f32x2 %0, %1, %2;" : "=l"(s1) : "l"(cur.y), "l"(gg)); // ch {4cq+2,4cq+3}

        // this lane's 8 W values: 2 LDS.128 (2 distinct addresses per warp)
        const float4* wr = (const float4*)(swn[wid] + k * CMID_ + 8 * wh);
        const float4 Wa = wr[0];
        const float4 Wb = wr[1];
        unsigned long long w0, w1, w2, w3, w4, w5, w6, w7;
        asm("mov.b64 %0, {%1, %1};" : "=l"(w0) : "f"(Wa.x));
        asm("mov.b64 %0, {%1, %1};" : "=l"(w1) : "f"(Wa.y));
        asm("mov.b64 %0, {%1, %1};" : "=l"(w2) : "f"(Wa.z));
        asm("mov.b64 %0, {%1, %1};" : "=l"(w3) : "f"(Wa.w));
        asm("mov.b64 %0, {%1, %1};" : "=l"(w4) : "f"(Wb.x));
        asm("mov.b64 %0, {%1, %1};" : "=l"(w5) : "f"(Wb.y));
        asm("mov.b64 %0, {%1, %1};" : "=l"(w6) : "f"(Wb.z));
        asm("mov.b64 %0, {%1, %1};" : "=l"(w7) : "f"(Wb.w));

        asm("fma.rn.f32x2 %0, %1, %2, %3;" : "=l"(acc[ 0]) : "l"(s0), "l"(w0), "l"(acc[ 0]));
        asm("fma.rn.f32x2 %0, %1, %2, %3;" : "=l"(acc[ 1]) : "l"(s0), "l"(w1), "l"(acc[ 1]));
        asm("fma.rn.f32x2 %0, %1, %2, %3;" : "=l"(acc[ 2]) : "l"(s0), "l"(w2), "l"(acc[ 2]));
        asm("fma.rn.f32x2 %0, %1, %2, %3;" : "=l"(acc[ 3]) : "l"(s0), "l"(w3), "l"(acc[ 3]));
        asm("fma.rn.f32x2 %0, %1, %2, %3;" : "=l"(acc[ 4]) : "l"(s0), "l"(w4), "l"(acc[ 4]));
        asm("fma.rn.f32x2 %0, %1, %2, %3;" : "=l"(acc[ 5]) : "l"(s0), "l"(w5), "l"(acc[ 5]));
        asm("fma.rn.f32x2 %0, %1, %2, %3;" : "=l"(acc[ 6]) : "l"(s0), "l"(w6), "l"(acc[ 6]));
        asm("fma.rn.f32x2 %0, %1, %2, %3;" : "=l"(acc[ 7]) : "l"(s0), "l"(w7), "l"(acc[ 7]));
        asm("fma.rn.f32x2 %0, %1, %2, %3;" : "=l"(acc[ 8]) : "l"(s1), "l"(w0), "l"(acc[ 8]));
        asm("fma.rn.f32x2 %0, %1, %2, %3;" : "=l"(acc[ 9]) : "l"(s1), "l"(w1), "l"(acc[ 9]));
        asm("fma.rn.f32x2 %0, %1, %2, %3;" : "=l"(acc[10]) : "l"(s1), "l"(w2), "l"(acc[10]));
        asm("fma.rn.f32x2 %0, %1, %2, %3;" : "=l"(acc[11]) : "l"(s1), "l"(w3), "l"(acc[11]));
        asm("fma.rn.f32x2 %0, %1, %2, %3;" : "=l"(acc[12]) : "l"(s1), "l"(w4), "l"(acc[12]));
        asm("fma.rn.f32x2 %0, %1, %2, %3;" : "=l"(acc[13]) : "l"(s1), "l"(w5), "l"(acc[13]));
        asm("fma.rn.f32x2 %0, %1, %2, %3;" : "=l"(acc[14]) : "l"(s1), "l"(w6), "l"(acc[14]));
        asm("fma.rn.f32x2 %0, %1, %2, %3;" : "=l"(acc[15]) : "l"(s1), "l"(w7), "l"(acc[15]));
    }

    // ---- epilogue: swizzled smem bounce, then fully-coalesced STG ----
    // Lane's 32 outputs as 8 chunks of 4 floats: chunk i (r=i>>1, q=i&1) =
    // out[4cq+r][8wh+4q .. +4]:
    //   r=0: lo halves of acc[4q..4q+3]      r=1: hi halves of acc[4q..4q+3]
    //   r=2: lo halves of acc[8+4q..8+4q+3]  r=3: hi halves of same
    // Stored in lane-private region (lane*32) at swizzled slot (i+lane)&7:
    // store phases conflict-free; flush phases have a benign 2-way conflict.
    {
        float* sb = sout[wid] + lane * 32;
        #pragma unroll
        for (int i = 0; i < 8; i++) {
            const int r  = i >> 1;
            const int q  = i & 1;
            const int ba = (r & 2) ? 8 : 0;            // acc bank (s0 vs s1 rows)
            const unsigned long long* a = acc + ba + 4 * q;
            float4 v;
            if (r & 1) {   // hi halves
                v = make_float4(((const float2*)&a[0])->y, ((const float2*)&a[1])->y,
                                ((const float2*)&a[2])->y, ((const float2*)&a[3])->y);
            } else {       // lo halves
                v = make_float4(((const float2*)&a[0])->x, ((const float2*)&a[1])->x,
                                ((const float2*)&a[2])->x, ((const float2*)&a[3])->x);
            }
            const int ip = (i + lane) & 7;             // swizzled chunk slot
            *(float4*)(sb + ip * 4) = v;
        }
    }
    __syncwarp();
    // Coalesced flush (FLOAT units): lane handles global floats
    // flat = j*128 + lane*4. Output (c,w): c = flat>>4, w = flat&15.
    // Source lane L = (c>>2) | ((w>>3)<<4); chunk i = ((c&3)<<1) | ((w>>2)&1);
    // physical slot (i+L)&7. STG: 512B contiguous per j (4 lines).
    {
        float* o = out + (size_t)p * (C_ * CMID_);
        #pragma unroll
        for (int j = 0; j < 8; j++) {
            const int flat = j * 128 + lane * 4;       // global float index
            const int c    = flat >> 4;
            const int w    = flat & 15;
            const int L    = (c >> 2) | ((w >> 3) << 4);
            const int i    = ((c & 3) << 1) | ((w >> 2) & 1);
            const int ip   = (i + L) & 7;
            const float4 v = *(const float4*)(sout[wid] + L * 32 + ip * 4);
            *(float4*)(o + flat) = v;
        }
    }
}

extern "C" void kernel_launch(void* const* d_in, const int* in_sizes, int n_in,
                              void* d_out, int out_size) {
    const float* feat = (const float*)d_in[0];
    const void*  inds = d_in[1];
    const float* guid = (const float*)d_in[2];
    const float* wn   = (const float*)d_in[3];
    float* out = (float*)d_out;

    detect_idx_kernel<<<1, 32>>>((const unsigned int*)inds);
    pcf_kernel<<<(B_ * M_) / 4, 128>>>(feat, inds, guid, wn, out);
}

// round 14
// speedup vs baseline: 1.1016x; 1.1016x over previous
#include <cuda_runtime.h>
#include <cstdint>

// Problem shape (fixed for this dataset entry)
#define B_    2
#define N_    50000
#define C_    64
#define M_    50000
#define K_    16
#define H_    8
#define CMID_ 16
#define PF    4    // gather prefetch depth

// Runtime-detected index width flag (int64 vs int32), set by detect kernel.
__device__ int g_idx_is64;

__global__ void detect_idx_kernel(const unsigned int* __restrict__ w) {
    if (threadIdx.x == 0 && blockIdx.x == 0) {
        int is64 = 1;
        #pragma unroll 1
        for (int i = 0; i < 256; i++) {
            if (w[2 * i + 1] != 0u) { is64 = 0; break; }
        }
        g_idx_is64 = is64;
    }
}

// One WARP per point; 4 points per 128-thread CTA.
// Compute loop = the proven 131us R12 loop, UNCHANGED:
//   lane l owns channels {2l, 2l+1} and all 16 w; zero-dup LDG.64 gather,
//   4 uniform LDS.128 per k for W, scalar guid LDS, 16 fma.rn.f32x2 per k.
// Epilogue = R12's swizzled smem bounce -> fully-coalesced STG.128.
// CHANGED vs R12 (occupancy/BW, the measured limiter):
//   1. smem union: the 4KB/warp output bounce REUSES the weightnet+guidance
//      staging blob (dead after the k-loop; warp-private so program order
//      guarantees safety). 23KB -> 16.3KB per CTA => 9 -> 13 CTAs/SM.
//   2. __stcs on output stores (write-once stream, evict-first) and __ldcs
//      on wn/guid staging reads (read-once streams) to keep L2 for feat.
__global__ void __launch_bounds__(128)
pcf_kernel(const float* __restrict__ feat,
           const void*  __restrict__ inds_raw,
           const float* __restrict__ guid,
           const float* __restrict__ wn,
           float* __restrict__ out)
{
    // Per-warp 4KB blob:
    //   phase 1 (k-loop):  [0,1KB) weightnet, [1KB,1.5KB) guidance
    //   phase 2 (epilogue): whole 4KB = output bounce
    __shared__ __align__(16) float sblob[4][1024];
    __shared__ int sidx[4][K_];

    const int wid  = threadIdx.x >> 5;
    const int lane = threadIdx.x & 31;
    const int p    = blockIdx.x * 4 + wid;      // point id in [0, B*M)
    const int b    = (p >= M_) ? 1 : 0;
    const int hd   = lane >> 2;                 // head of channels {2l,2l+1}

    float* swn = sblob[wid];          // 256 floats
    float* sgd = sblob[wid] + 256;    // 128 floats
    float* sou = sblob[wid];          // 1024 floats (reused after loop)

    // ---- per-warp staging: weightnet (1KB), guidance (512B), indices ----
    {
        const float4* wsrc = (const float4*)(wn + (size_t)p * (K_ * CMID_));
        float4* wdst = (float4*)swn;
        wdst[lane]      = __ldcs(wsrc + lane);
        wdst[lane + 32] = __ldcs(wsrc + lane + 32);
        ((float4*)sgd)[lane] =
            __ldcs(((const float4*)(guid + (size_t)p * (K_ * H_))) + lane);
        if (lane < K_) {
            long long idx;
            if (g_idx_is64) idx = ((const long long*)inds_raw)[(size_t)p * K_ + lane];
            else            idx = (long long)((const int*)inds_raw)[(size_t)p * K_ + lane];
            sidx[wid][lane] = (int)idx;
        }
    }
    __syncwarp();

    // lane-fixed channel offset: feature row base + channel 2*lane
    const float* fb = feat + (size_t)b * ((size_t)N_ * C_) + 2 * lane;

    // ---- prefetch pipeline for the gather (zero-dup LDG.64) ----
    float2 gbuf[PF];
    #pragma unroll
    for (int i = 0; i < PF; i++)
        gbuf[i] = *(const float2*)(fb + (size_t)sidx[wid][i] * C_);

    unsigned long long acc[16];
    #pragma unroll
    for (int i = 0; i < 16; i++) acc[i] = 0ull;

    #pragma unroll
    for (int k = 0; k < K_; k++) {
        float2 f = gbuf[k % PF];
        if (k + PF < K_)
            gbuf[k % PF] = *(const float2*)(fb + (size_t)sidx[wid][k + PF] * C_);

        const float g = sgd[k * H_ + hd];       // broadcast (8 distinct words)
        const float s0 = f.x * g;
        const float s1 = f.y * g;
        unsigned long long g0, g1;
        asm("mov.b64 %0, {%1, %1};" : "=l"(g0) : "f"(s0));
        asm("mov.b64 %0, {%1, %1};" : "=l"(g1) : "f"(s1));

        // W row k: 16 floats = 4 uniform LDS.128 -> 8 packed {w2j, w2j+1}
        const ulonglong2* wr = (const ulonglong2*)(swn + k * CMID_);
        ulonglong2 A = wr[0];   // {w0w1, w2w3}
        ulonglong2 Bv = wr[1];  // {w4w5, w6w7}
        ulonglong2 Cv = wr[2];  // {w8w9, w10w11}
        ulonglong2 Dv = wr[3];  // {w12w13, w14w15}

        asm("fma.rn.f32x2 %0, %1, %2, %3;" : "=l"(acc[ 0]) : "l"(g0), "l"(A.x),  "l"(acc[ 0]));
        asm("fma.rn.f32x2 %0, %1, %2, %3;" : "=l"(acc[ 1]) : "l"(g0), "l"(A.y),  "l"(acc[ 1]));
        asm("fma.rn.f32x2 %0, %1, %2, %3;" : "=l"(acc[ 2]) : "l"(g0), "l"(Bv.x), "l"(acc[ 2]));
        asm("fma.rn.f32x2 %0, %1, %2, %3;" : "=l"(acc[ 3]) : "l"(g0), "l"(Bv.y), "l"(acc[ 3]));
        asm("fma.rn.f32x2 %0, %1, %2, %3;" : "=l"(acc[ 4]) : "l"(g0), "l"(Cv.x), "l"(acc[ 4]));
        asm("fma.rn.f32x2 %0, %1, %2, %3;" : "=l"(acc[ 5]) : "l"(g0), "l"(Cv.y), "l"(acc[ 5]));
        asm("fma.rn.f32x2 %0, %1, %2, %3;" : "=l"(acc[ 6]) : "l"(g0), "l"(Dv.x), "l"(acc[ 6]));
        asm("fma.rn.f32x2 %0, %1, %2, %3;" : "=l"(acc[ 7]) : "l"(g0), "l"(Dv.y), "l"(acc[ 7]));
        asm("fma.rn.f32x2 %0, %1, %2, %3;" : "=l"(acc[ 8]) : "l"(g1), "l"(A.x),  "l"(acc[ 8]));
        asm("fma.rn.f32x2 %0, %1, %2, %3;" : "=l"(acc[ 9]) : "l"(g1), "l"(A.y),  "l"(acc[ 9]));
        asm("fma.rn.f32x2 %0, %1, %2, %3;" : "=l"(acc[10]) : "l"(g1), "l"(Bv.x), "l"(acc[10]));
        asm("fma.rn.f32x2 %0, %1, %2, %3;" : "=l"(acc[11]) : "l"(g1), "l"(Bv.y), "l"(acc[11]));
        asm("fma.rn.f32x2 %0, %1, %2, %3;" : "=l"(acc[12]) : "l"(g1), "l"(Cv.x), "l"(acc[12]));
        asm("fma.rn.f32x2 %0, %1, %2, %3;" : "=l"(acc[13]) : "l"(g1), "l"(Cv.y), "l"(acc[13]));
        asm("fma.rn.f32x2 %0, %1, %2, %3;" : "=l"(acc[14]) : "l"(g1), "l"(Dv.x), "l"(acc[14]));
        asm("fma.rn.f32x2 %0, %1, %2, %3;" : "=l"(acc[15]) : "l"(g1), "l"(Dv.y), "l"(acc[15]));
    }
    __syncwarp();   // all lanes done reading swn/sgd before the bounce reuses it

    // ---- epilogue: swizzled smem bounce (reusing the blob), coalesced STG ----
    // Lane L's 32-float flat block (row 2L = acc[0..7] -> floats 0..15,
    // row 2L+1 = acc[8..15] -> floats 16..31) lives at sou + L*32.
    // Chunk i (floats 4i..4i+3 = {acc[2i], acc[2i+1]}) stored at swizzled
    // slot ip=(i+L)&7. Per 8-lane phase all ip distinct -> conflict-free.
    {
        float* sb = sou + lane * 32;
        #pragma unroll
        for (int i = 0; i < 8; i++) {
            const int ip = (i + lane) & 7;           // swizzled chunk slot
            *(ulonglong2*)(sb + ip * 4) =
                make_ulonglong2(acc[2 * i], acc[2 * i + 1]);
        }
    }
    __syncwarp();
    // Coalesced flush (FLOAT units): lane handles global floats
    // flat = j*128 + lane*4. Source: lane s = flat/32, chunk i = (flat%32)/4,
    // physical slot ip = (i+s)&7. Conflict-free. STG: 512B contiguous per j.
    {
        float* o = out + (size_t)p * (C_ * CMID_);
        #pragma unroll
        for (int j = 0; j < 8; j++) {
            const int flat = j * 128 + lane * 4;     // global float index
            const int s    = flat >> 5;              // source lane (32 floats ea)
            const int i    = (flat >> 2) & 7;        // chunk within source block
            const int ip   = (i + s) & 7;            // swizzled slot
            const float4 v = *(const float4*)(sou + s * 32 + ip * 4);
            __stcs((float4*)(o + flat), v);          // streaming store
        }
    }
}

extern "C" void kernel_launch(void* const* d_in, const int* in_sizes, int n_in,
                              void* d_out, int out_size) {
    const float* feat = (const float*)d_in[0];
    const void*  inds = d_in[1];
    const float* guid = (const float*)d_in[2];
    const float* wn   = (const float*)d_in[3];
    float* out = (float*)d_out;

    detect_idx_kernel<<<1, 32>>>((const unsigned int*)inds);
    pcf_kernel<<<(B_ * M_) / 4, 128>>>(feat, inds, guid, wn, out);
}